// round 13
// baseline (speedup 1.0000x reference)
#include <cuda_runtime.h>
#include <cuda_bf16.h>
#include <math.h>
#include <cstdint>

// ---------------- problem constants ----------------
#define B_    256
#define C_    1024
#define S_    49
#define D_    1024
#define L_    2
#define H_    2
#define HD_   512
#define FF_   1024
#define OUT_  1024
#define M_    (B_ * S_)   // 12544 rows
#define KHEAD (S_ * D_)   // 50176

// ---------------- device scratch (no allocs allowed) ----------------
__device__ float g_h  [M_ * D_];
__device__ float g_qkv[M_ * 3 * D_];
__device__ __nv_bfloat16 g_ah[M_ * D_];
__device__ __nv_bfloat16 g_al[M_ * D_];
__device__ __nv_bfloat16 g_bh[M_ * FF_];
__device__ __nv_bfloat16 g_bl[M_ * FF_];
__device__ __nv_bfloat16 g_wh[L_ * 6 * D_ * D_];
__device__ __nv_bfloat16 g_wl[L_ * 6 * D_ * D_];
__device__ float g_part[16 * B_ * OUT_];

// ---------------- helpers ----------------
__device__ __forceinline__ float gelu_new(float x) {
    float x3 = x * x * x;
    return 0.5f * x * (1.f + tanhf(0.7978845608028654f * (x + 0.044715f * x3)));
}
__device__ __forceinline__ void split2(float v, __nv_bfloat16& h, __nv_bfloat16& l) {
    h = __float2bfloat16(v);
    l = __float2bfloat16(v - __bfloat162float(h));
}

__device__ __forceinline__ void mma16816(float* d, const uint32_t* a, const uint32_t* b) {
    asm volatile(
        "mma.sync.aligned.m16n8k16.row.col.f32.bf16.bf16.f32 "
        "{%0,%1,%2,%3}, {%4,%5,%6,%7}, {%8,%9}, {%0,%1,%2,%3};"
        : "+f"(d[0]), "+f"(d[1]), "+f"(d[2]), "+f"(d[3])
        : "r"(a[0]), "r"(a[1]), "r"(a[2]), "r"(a[3]), "r"(b[0]), "r"(b[1]));
}
__device__ __forceinline__ void ldm4(uint32_t* r, uint32_t addr) {
    asm volatile("ldmatrix.sync.aligned.m8n8.x4.shared.b16 {%0,%1,%2,%3}, [%4];"
                 : "=r"(r[0]), "=r"(r[1]), "=r"(r[2]), "=r"(r[3]) : "r"(addr));
}
__device__ __forceinline__ void ldm4t(uint32_t* r, uint32_t addr) {
    asm volatile("ldmatrix.sync.aligned.m8n8.x4.trans.shared.b16 {%0,%1,%2,%3}, [%4];"
                 : "=r"(r[0]), "=r"(r[1]), "=r"(r[2]), "=r"(r[3]) : "r"(addr));
}

// ================= mma.sync bf16 split GEMM (round-12, unchanged) =================
#define PADA   80
#define PADB2  272
#define A128   (128 * PADA)            // 10240 per matrix
#define BMAT   (32 * PADB2)            // 8704
#define BOFF   (2 * A128)              // 20480
#define STAGEB (2 * A128 + 2 * BMAT)   // 37888
#define SMEM_GEMM (3 * STAGEB)         // 113664

template<int EPI>
__global__ __launch_bounds__(256, 2) void mma_gemm(
    const __nv_bfloat16* __restrict__ Ah, const __nv_bfloat16* __restrict__ Al,
    const __nv_bfloat16* __restrict__ Bh, const __nv_bfloat16* __restrict__ Bl,
    const float* __restrict__ bias, const float* __restrict__ R, float* __restrict__ C,
    int ld, int ldb, int kIters, int ldc,
    __nv_bfloat16* __restrict__ Ch, __nv_bfloat16* __restrict__ Cl)
{
    extern __shared__ char smem[];
    uint32_t sm0;
    asm("{ .reg .u64 t; cvta.to.shared.u64 t, %1; cvt.u32.u64 %0, t; }" : "=r"(sm0) : "l"(smem));
    int tid = threadIdx.x, wid = tid >> 5, lane = tid & 31;
    int bn = blockIdx.x, bm = blockIdx.y;

    const __nv_bfloat16* srcs[8];
    uint32_t dsts[8];
#pragma unroll
    for (int j = 0; j < 8; j++) {
        int slot = tid + j * 256;
        if (j < 4) {
            int mat = slot >> 9;
            int r   = (slot >> 2) & 127;
            int sg  = slot & 3;
            const __nv_bfloat16* base = mat ? Al : Ah;
            srcs[j] = base + (size_t)(bm * 128 + r) * ld + sg * 8;
            dsts[j] = sm0 + mat * A128 + r * PADA + sg * 16;
        } else {
            int s2  = slot - 1024;
            int mat = s2 >> 9;
            int r   = (s2 >> 4) & 31;
            int sg  = s2 & 15;
            const __nv_bfloat16* base = mat ? Bl : Bh;
            srcs[j] = base + (size_t)r * ldb + bn * 128 + sg * 8;
            dsts[j] = sm0 + BOFF + mat * BMAT + r * PADB2 + sg * 16;
        }
    }

#define LOAD_STAGE(stg)                                                            \
    {                                                                              \
        _Pragma("unroll")                                                          \
        for (int j = 0; j < 8; j++) {                                              \
            asm volatile("cp.async.cg.shared.global [%0], [%1], 16;"               \
                         :: "r"(dsts[j] + (stg) * STAGEB), "l"(srcs[j]) : "memory"); \
            srcs[j] += (j < 4) ? 32 : (size_t)32 * ldb;                            \
        }                                                                          \
        asm volatile("cp.async.commit_group;" ::: "memory");                       \
    }

    int warp_m = wid >> 2, warp_n = wid & 3;
    int g = lane >> 2, tg = lane & 3;
    int t8 = lane >> 3, tl = lane & 7;
    uint32_t aBase = (uint32_t)((warp_m * 64 + (t8 & 1) * 8 + tl) * PADA + (t8 >> 1) * 16);
    uint32_t bBase = (uint32_t)(((t8 & 1) * 8 + tl) * PADB2 + (warp_n * 32 + (t8 >> 1) * 8) * 2);

    float acc[4][4][4];
#pragma unroll
    for (int mt = 0; mt < 4; mt++)
#pragma unroll
        for (int nt = 0; nt < 4; nt++)
#pragma unroll
            for (int j = 0; j < 4; j++) acc[mt][nt][j] = 0.f;

    LOAD_STAGE(0);
    LOAD_STAGE(1);

    for (int it = 0; it < kIters; it++) {
        asm volatile("cp.async.wait_group 1;" ::: "memory");
        __syncthreads();
        uint32_t st = sm0 + (it % 3) * STAGEB;

#pragma unroll
        for (int ks = 0; ks < 2; ks++) {
            uint32_t bh[4][2], bl[4][2];
#pragma unroll
            for (int p = 0; p < 2; p++) {
                uint32_t rb = st + BOFF + bBase + ks * (16 * PADB2) + p * 32;
                uint32_t r4[4];
                ldm4t(r4, rb);
                bh[2 * p][0] = r4[0]; bh[2 * p][1] = r4[1];
                bh[2 * p + 1][0] = r4[2]; bh[2 * p + 1][1] = r4[3];
                ldm4t(r4, rb + BMAT);
                bl[2 * p][0] = r4[0]; bl[2 * p][1] = r4[1];
                bl[2 * p + 1][0] = r4[2]; bl[2 * p + 1][1] = r4[3];
            }
#pragma unroll
            for (int mt = 0; mt < 4; mt++) {
                uint32_t ra = st + aBase + mt * (16 * PADA) + ks * 32;
                uint32_t ah[4], al[4];
                ldm4(ah, ra);
                ldm4(al, ra + A128);
#pragma unroll
                for (int nt = 0; nt < 4; nt++) {
                    mma16816(acc[mt][nt], ah, bh[nt]);
                    mma16816(acc[mt][nt], ah, bl[nt]);
                    mma16816(acc[mt][nt], al, bh[nt]);
                }
            }
        }
        if (it + 2 < kIters) {
            LOAD_STAGE((it + 2) % 3);
        } else {
            asm volatile("cp.async.commit_group;" ::: "memory");
        }
    }

#pragma unroll
    for (int mt = 0; mt < 4; mt++) {
        int row0 = bm * 128 + warp_m * 64 + mt * 16 + g;
#pragma unroll
        for (int nt = 0; nt < 4; nt++) {
            int col = bn * 128 + warp_n * 32 + nt * 8 + tg * 2;
#pragma unroll
            for (int half = 0; half < 2; half++) {
                int row = row0 + half * 8;
                float2 v = make_float2(acc[mt][nt][half * 2], acc[mt][nt][half * 2 + 1]);
                if (EPI == 1) {
                    const float2 r = *(const float2*)(R + (size_t)row * ldc + col);
                    v.x += r.x; v.y += r.y;
                }
                if (EPI == 4) {
                    const float2 b = *(const float2*)(bias + col);
                    const float2 r = *(const float2*)(R + (size_t)row * ldc + col);
                    v.x += b.x + r.x; v.y += b.y + r.y;
                }
                if (EPI == 5) {
                    const float2 b = *(const float2*)(bias + col);
                    v.x = gelu_new(v.x + b.x); v.y = gelu_new(v.y + b.y);
                    __nv_bfloat162 hh, ll;
                    split2(v.x, hh.x, ll.x);
                    split2(v.y, hh.y, ll.y);
                    *(__nv_bfloat162*)(Ch + (size_t)row * ldc + col) = hh;
                    *(__nv_bfloat162*)(Cl + (size_t)row * ldc + col) = ll;
                } else {
                    *(float2*)(C + (size_t)row * ldc + col) = v;
                }
            }
        }
    }
#undef LOAD_STAGE
}

// ================= head GEMM v2: encoder-shaped (128-row tile, 2 CTAs/SM) =================
// grid (8, 2, 16): bn = N/128, bm = M/128, bz = K-split. In-kernel fp32->bf16 B conversion.
#define H2_ASTG  (2 * A128)                 // 20480 per stage (Ah+Al)
#define H2_BOFF  (3 * H2_ASTG)              // 61440
#define H2_BBUF  (2 * BMAT)                 // 17408
#define SMEM_HEAD (H2_BOFF + 2 * H2_BBUF)   // 96256
#define HK_ITERS 98

__global__ __launch_bounds__(256, 2) void head_gemm(
    const __nv_bfloat16* __restrict__ Ah, const __nv_bfloat16* __restrict__ Al,
    const float* __restrict__ W, float* __restrict__ Cpart)
{
    extern __shared__ char smem[];
    uint32_t sm0;
    asm("{ .reg .u64 t; cvta.to.shared.u64 t, %1; cvt.u32.u64 %0, t; }" : "=r"(sm0) : "l"(smem));
    int tid = threadIdx.x, wid = tid >> 5, lane = tid & 31;
    int bn = blockIdx.x, bm = blockIdx.y, bz = blockIdx.z;
    size_t kStart = (size_t)bz * HK_ITERS * 32;

    // A loader: 4 x 16B cp.async per thread (2 mats x 128 rows x 4 segs)
    const __nv_bfloat16* asrc[4];
    uint32_t adst[4];
#pragma unroll
    for (int j = 0; j < 4; j++) {
        int slot = tid + j * 256;
        int mat = slot >> 9;
        int r   = (slot >> 2) & 127;
        int sg  = slot & 3;
        const __nv_bfloat16* base = mat ? Al : Ah;
        asrc[j] = base + (size_t)(bm * 128 + r) * KHEAD + kStart + sg * 8;
        adst[j] = sm0 + mat * A128 + r * PADA + sg * 16;
    }
#define LOADA(stg)                                                                \
    {                                                                             \
        _Pragma("unroll")                                                         \
        for (int j = 0; j < 4; j++) {                                             \
            asm volatile("cp.async.cg.shared.global [%0], [%1], 16;"              \
                         :: "r"(adst[j] + (stg) * H2_ASTG), "l"(asrc[j]) : "memory"); \
            asrc[j] += 32;                                                        \
        }                                                                         \
        asm volatile("cp.async.commit_group;" ::: "memory");                      \
    }

    int brow = tid >> 3, bseg = tid & 7;
    const float* bsrc = W + (kStart + brow) * 1024 + bn * 128 + bseg * 16;
    uint32_t bsm = sm0 + H2_BOFF + brow * PADB2 + bseg * 32;

    int warp_m = wid >> 2, warp_n = wid & 3;
    int g = lane >> 2, tg = lane & 3;
    int t8 = lane >> 3, tl = lane & 7;
    uint32_t aBase = (uint32_t)((warp_m * 64 + (t8 & 1) * 8 + tl) * PADA + (t8 >> 1) * 16);
    uint32_t bBase = (uint32_t)(((t8 & 1) * 8 + tl) * PADB2 + (warp_n * 32 + (t8 >> 1) * 8) * 2);

    float acc[4][4][4];
#pragma unroll
    for (int mt = 0; mt < 4; mt++)
#pragma unroll
        for (int nt = 0; nt < 4; nt++)
#pragma unroll
            for (int j = 0; j < 4; j++) acc[mt][nt][j] = 0.f;

    LOADA(0);
    LOADA(1);
    float4 br[4];
#pragma unroll
    for (int i = 0; i < 4; i++) br[i] = *(const float4*)(bsrc + i * 4);

    for (int it = 0; it < HK_ITERS; it++) {
        // convert+store B regs into buf[it&1] BEFORE the barrier (safe: prev iter
        // reads buf[(it-1)&1]; older reads of buf[it&1] fenced by prev iter's sync)
        uint32_t bd = bsm + (it & 1) * H2_BBUF;
#pragma unroll
        for (int i = 0; i < 4; i++) {
            __nv_bfloat162 h0, h1, l0, l1;
            split2(br[i].x, h0.x, l0.x); split2(br[i].y, h0.y, l0.y);
            split2(br[i].z, h1.x, l1.x); split2(br[i].w, h1.y, l1.y);
            uint32_t hvx = *(uint32_t*)&h0, hvy = *(uint32_t*)&h1;
            uint32_t lvx = *(uint32_t*)&l0, lvy = *(uint32_t*)&l1;
            asm volatile("st.shared.v2.u32 [%0], {%1, %2};" :: "r"(bd + i * 8), "r"(hvx), "r"(hvy) : "memory");
            asm volatile("st.shared.v2.u32 [%0], {%1, %2};" :: "r"(bd + BMAT + i * 8), "r"(lvx), "r"(lvy) : "memory");
        }
        if (it + 1 < HK_ITERS) {
            const float* nb = bsrc + (size_t)(it + 1) * 32 * 1024;
#pragma unroll
            for (int i = 0; i < 4; i++) br[i] = *(const float4*)(nb + i * 4);
        }
        asm volatile("cp.async.wait_group 1;" ::: "memory");
        __syncthreads();

        uint32_t st = sm0 + (it % 3) * H2_ASTG;
        uint32_t bb = sm0 + H2_BOFF + (it & 1) * H2_BBUF;
#pragma unroll
        for (int ks = 0; ks < 2; ks++) {
            uint32_t bh[4][2], bl[4][2];
#pragma unroll
            for (int p = 0; p < 2; p++) {
                uint32_t rb = bb + bBase + ks * (16 * PADB2) + p * 32;
                uint32_t r4[4];
                ldm4t(r4, rb);
                bh[2 * p][0] = r4[0]; bh[2 * p][1] = r4[1];
                bh[2 * p + 1][0] = r4[2]; bh[2 * p + 1][1] = r4[3];
                ldm4t(r4, rb + BMAT);
                bl[2 * p][0] = r4[0]; bl[2 * p][1] = r4[1];
                bl[2 * p + 1][0] = r4[2]; bl[2 * p + 1][1] = r4[3];
            }
#pragma unroll
            for (int mt = 0; mt < 4; mt++) {
                uint32_t ra = st + aBase + mt * (16 * PADA) + ks * 32;
                uint32_t ah[4], al[4];
                ldm4(ah, ra);
                ldm4(al, ra + A128);
#pragma unroll
                for (int nt = 0; nt < 4; nt++) {
                    mma16816(acc[mt][nt], ah, bh[nt]);
                    mma16816(acc[mt][nt], ah, bl[nt]);
                    mma16816(acc[mt][nt], al, bh[nt]);
                }
            }
        }
        if (it + 2 < HK_ITERS) {
            LOADA((it + 2) % 3);
        } else {
            asm volatile("cp.async.commit_group;" ::: "memory");
        }
    }

    float* Cp = Cpart + (size_t)bz * (B_ * OUT_);
#pragma unroll
    for (int mt = 0; mt < 4; mt++) {
        int row0 = bm * 128 + warp_m * 64 + mt * 16 + g;
#pragma unroll
        for (int nt = 0; nt < 4; nt++) {
            int col = bn * 128 + warp_n * 32 + nt * 8 + tg * 2;
#pragma unroll
            for (int half = 0; half < 2; half++) {
                int row = row0 + half * 8;
                *(float2*)(Cp + (size_t)row * 1024 + col) =
                    make_float2(acc[mt][nt][half * 2], acc[mt][nt][half * 2 + 1]);
            }
        }
    }
#undef LOADA
}

// ---------------- merged weight conversion ----------------
__global__ void convAll(const float* __restrict__ wq, const float* __restrict__ wk,
                        const float* __restrict__ wv, const float* __restrict__ wo,
                        const float* __restrict__ w1, const float* __restrict__ w2,
                        __nv_bfloat16* __restrict__ Wh, __nv_bfloat16* __restrict__ Wl) {
    int unit = blockIdx.x >> 10;
    int blk  = blockIdx.x & 1023;
    int layer = unit / 6, widx = unit % 6;
    const float* srcs[6] = {wq, wk, wv, wo, w1, w2};
    const float* src = srcs[widx] + (size_t)layer * D_ * D_;
    size_t idx = (size_t)blk * 1024 + threadIdx.x * 4;
    int k = (int)(idx >> 10);
    int n = (int)(idx & 1023);
    int Nout  = (widx < 3) ? 3072 : 1024;
    int coloff = (widx < 3) ? widx * 1024 : 0;
    size_t dbase = (size_t)layer * 6 * D_ * D_ + ((widx < 3) ? 0 : (size_t)widx * D_ * D_);
    size_t o = dbase + (size_t)k * Nout + coloff + n;
    float4 v = *(const float4*)(src + idx);
    __nv_bfloat162 h0, h1, l0, l1;
    split2(v.x, h0.x, l0.x); split2(v.y, h0.y, l0.y);
    split2(v.z, h1.x, l1.x); split2(v.w, h1.y, l1.y);
    *(__nv_bfloat162*)(Wh + o) = h0;
    *(__nv_bfloat162*)(Wh + o + 2) = h1;
    *(__nv_bfloat162*)(Wl + o) = l0;
    *(__nv_bfloat162*)(Wl + o + 2) = l1;
}

// ---------------- head reduce ----------------
__global__ void head_reduce(const float* __restrict__ parts, const float* __restrict__ bias,
                            float* __restrict__ out) {
    int i = blockIdx.x * blockDim.x + threadIdx.x;
    float s = bias[i & (OUT_ - 1)];
#pragma unroll
    for (int z = 0; z < 16; z++) s += parts[(size_t)z * (B_ * OUT_) + i];
    out[i] = fmaxf(s, 0.f);
}

// ---------------- embed ----------------
__global__ void embed_kernel(const float* __restrict__ x, const float* __restrict__ pos) {
    __shared__ float tile[64][S_ + 1];
    int b = blockIdx.y;
    int d0 = blockIdx.x * 64;
    int tid = threadIdx.x;
    for (int idx = tid; idx < 64 * S_; idx += 256) {
        int dr = idx / S_, s = idx % S_;
        tile[dr][s] = x[(size_t)(b * C_ + d0 + dr) * S_ + s];
    }
    __syncthreads();
    for (int idx = tid; idx < S_ * 64; idx += 256) {
        int s = idx >> 6, dr = idx & 63;
        g_h[(size_t)(b * S_ + s) * D_ + d0 + dr] = tile[dr][s] + pos[s * D_ + d0 + dr];
    }
}

// ---------------- layernorm (vectorized) ----------------
__global__ void ln_split_kernel(const float* __restrict__ in,
                                __nv_bfloat16* __restrict__ oh, __nv_bfloat16* __restrict__ ol,
                                const float* __restrict__ sc, const float* __restrict__ bi) {
    int row = blockIdx.x;
    int tid = threadIdx.x;
    int d0 = tid * 4;
    float4 v = *(const float4*)(in + (size_t)row * D_ + d0);
    float s = v.x + v.y + v.z + v.w;
    float ss = v.x * v.x + v.y * v.y + v.z * v.z + v.w * v.w;

    __shared__ float rs[8], rss[8];
    int lane = tid & 31, w = tid >> 5;
#pragma unroll
    for (int o = 16; o; o >>= 1) {
        s  += __shfl_xor_sync(0xffffffffu, s,  o);
        ss += __shfl_xor_sync(0xffffffffu, ss, o);
    }
    if (lane == 0) { rs[w] = s; rss[w] = ss; }
    __syncthreads();
    if (tid < 32) {
        float s2  = (tid < 8) ? rs[tid]  : 0.f;
        float ss2 = (tid < 8) ? rss[tid] : 0.f;
#pragma unroll
        for (int o = 4; o; o >>= 1) {
            s2  += __shfl_xor_sync(0xffffffffu, s2,  o);
            ss2 += __shfl_xor_sync(0xffffffffu, ss2, o);
        }
        if (tid == 0) { rs[0] = s2; rss[0] = ss2; }
    }
    __syncthreads();
    float mean = rs[0] * (1.f / 1024.f);
    float var  = rss[0] * (1.f / 1024.f) - mean * mean;
    float inv  = rsqrtf(var + 1e-5f);

    float4 scv = *(const float4*)(sc + d0);
    float4 biv = *(const float4*)(bi + d0);
    float r0 = (v.x - mean) * inv * scv.x + biv.x;
    float r1 = (v.y - mean) * inv * scv.y + biv.y;
    float r2 = (v.z - mean) * inv * scv.z + biv.z;
    float r3 = (v.w - mean) * inv * scv.w + biv.w;
    __nv_bfloat162 h0, h1, l0, l1;
    split2(r0, h0.x, l0.x); split2(r1, h0.y, l0.y);
    split2(r2, h1.x, l1.x); split2(r3, h1.y, l1.y);
    uint2 hv, lv;
    hv.x = *(uint32_t*)&h0; hv.y = *(uint32_t*)&h1;
    lv.x = *(uint32_t*)&l0; lv.y = *(uint32_t*)&l1;
    *(uint2*)(oh + (size_t)row * D_ + d0) = hv;
    *(uint2*)(ol + (size_t)row * D_ + d0) = lv;
}

// ---------------- fused attention: 4x4 register blocking ----------------
__global__ void attn_kernel() {
    int bh = blockIdx.x;
    int b  = bh >> 1;
    int hh = bh & 1;
    __shared__ float qs[52 * 65];
    __shared__ float ks[52 * 65];
    __shared__ float sc[52 * 50];
    int tid = threadIdx.x;
    const size_t baseQ = (size_t)b * S_ * 3072 + hh * HD_;

    for (int idx = tid; idx < 3 * 65; idx += 256) {
        qs[49 * 65 + idx] = 0.f;
        ks[49 * 65 + idx] = 0.f;
    }
    for (int idx = tid; idx < 3 * 50; idx += 256) sc[49 * 50 + idx] = 0.f;

    int tq = tid / 13, tk = tid - tq * 13;
    bool p1 = (tid < 169);
    int q0 = tq * 4, k0 = tk * 4;
    float acc[4][4];
#pragma unroll
    for (int i = 0; i < 4; i++)
#pragma unroll
        for (int j = 0; j < 4; j++) acc[i][j] = 0.f;

    for (int c = 0; c < 8; c++) {
        __syncthreads();
        for (int idx = tid; idx < S_ * 16; idx += 256) {
            int r = idx >> 4, f = idx & 15;
            const float* gp = g_qkv + baseQ + (size_t)r * 3072 + c * 64 + f * 4;
            float4 qv = *(const float4*)gp;
            float4 kv = *(const float4*)(gp + 1024);
            float* qd = &qs[r * 65 + f * 4];
            float* kd = &ks[r * 65 + f * 4];
            qd[0] = qv.x; qd[1] = qv.y; qd[2] = qv.z; qd[3] = qv.w;
            kd[0] = kv.x; kd[1] = kv.y; kd[2] = kv.z; kd[3] = kv.w;
        }
        __syncthreads();
        if (p1) {
#pragma unroll 4
            for (int d = 0; d < 64; d++) {
                float ra[4], rb[4];
#pragma unroll
                for (int i = 0; i < 4; i++) {
                    ra[i] = qs[(q0 + i) * 65 + d];
                    rb[i] = ks[(k0 + i) * 65 + d];
                }
#pragma unroll
                for (int i = 0; i < 4; i++)
#pragma unroll
                    for (int j = 0; j < 4; j++) acc[i][j] += ra[i] * rb[j];
            }
        }
    }
    __syncthreads();
    const float scale = 0.044194173824159216f;
    if (p1) {
#pragma unroll
        for (int i = 0; i < 4; i++)
#pragma unroll
            for (int j = 0; j < 4; j++) {
                int q = q0 + i, k = k0 + j;
                if (q < S_ && k < S_) sc[q * 50 + k] = acc[i][j] * scale;
            }
    }
    __syncthreads();

    if (tid < S_) {
        float mx = -1e30f;
        for (int k = 0; k < S_; k++) mx = fmaxf(mx, sc[tid * 50 + k]);
        float sum = 0.f;
        for (int k = 0; k < S_; k++) {
            float e = __expf(sc[tid * 50 + k] - mx);
            sc[tid * 50 + k] = e; sum += e;
        }
        float inv = 1.f / sum;
        for (int k = 0; k < S_; k++) sc[tid * 50 + k] *= inv;
    }

    int tq2 = tid >> 4, td = tid & 15;
    bool p2 = (tq2 < 13);
    int q2 = tq2 * 4, d0 = td * 4;
    const size_t baseO = (size_t)b * S_ * D_ + hh * HD_;

    for (int c = 0; c < 8; c++) {
        __syncthreads();
        for (int idx = tid; idx < S_ * 16; idx += 256) {
            int r = idx >> 4, f = idx & 15;
            float4 vv = *(const float4*)(g_qkv + baseQ + 2048 + (size_t)r * 3072 + c * 64 + f * 4);
            float* vd = &ks[r * 65 + f * 4];
            vd[0] = vv.x; vd[1] = vv.y; vd[2] = vv.z; vd[3] = vv.w;
        }
        __syncthreads();
        if (p2) {
            float a2[4][4];
#pragma unroll
            for (int i = 0; i < 4; i++)
#pragma unroll
                for (int j = 0; j < 4; j++) a2[i][j] = 0.f;
            for (int k = 0; k < S_; k++) {
                float ra[4], rb[4];
#pragma unroll
                for (int i = 0; i < 4; i++) ra[i] = sc[(q2 + i) * 50 + k];
#pragma unroll
                for (int j = 0; j < 4; j++) rb[j] = ks[k * 65 + d0 + j];
#pragma unroll
                for (int i = 0; i < 4; i++)
#pragma unroll
                    for (int j = 0; j < 4; j++) a2[i][j] += ra[i] * rb[j];
            }
#pragma unroll
            for (int i = 0; i < 4; i++) {
                int q = q2 + i;
                if (q < S_) {
                    size_t o = baseO + (size_t)q * D_ + c * 64 + d0;
                    __nv_bfloat162 h0, h1, l0, l1;
                    split2(a2[i][0], h0.x, l0.x);
                    split2(a2[i][1], h0.y, l0.y);
                    split2(a2[i][2], h1.x, l1.x);
                    split2(a2[i][3], h1.y, l1.y);
                    uint2 hv, lv;
                    hv.x = *(uint32_t*)&h0; hv.y = *(uint32_t*)&h1;
                    lv.x = *(uint32_t*)&l0; lv.y = *(uint32_t*)&l1;
                    *(uint2*)(g_ah + o) = hv;
                    *(uint2*)(g_al + o) = lv;
                }
            }
        }
    }
}

// ---------------- host orchestration ----------------
extern "C" void kernel_launch(void* const* d_in, const int* in_sizes, int n_in,
                              void* d_out, int out_size) {
    (void)in_sizes; (void)n_in; (void)out_size;
    const float* x      = (const float*)d_in[0];
    const float* pos    = (const float*)d_in[1];
    const float* ln1_s  = (const float*)d_in[2];
    const float* ln1_b  = (const float*)d_in[3];
    const float* wq     = (const float*)d_in[4];
    const float* wk     = (const float*)d_in[5];
    const float* wv     = (const float*)d_in[6];
    const float* wo     = (const float*)d_in[7];
    const float* ln2_s  = (const float*)d_in[8];
    const float* ln2_b  = (const float*)d_in[9];
    const float* w1     = (const float*)d_in[10];
    const float* b1     = (const float*)d_in[11];
    const float* w2     = (const float*)d_in[12];
    const float* b2     = (const float*)d_in[13];
    const float* lnf_s  = (const float*)d_in[14];
    const float* lnf_b  = (const float*)d_in[15];
    const float* head_w = (const float*)d_in[16];
    const float* head_b = (const float*)d_in[17];
    float* out = (float*)d_out;

    float *pH, *pQKV, *pPart;
    __nv_bfloat16 *pAh, *pAl, *pBh, *pBl, *pWh, *pWl;
    cudaGetSymbolAddress((void**)&pH,   g_h);
    cudaGetSymbolAddress((void**)&pQKV, g_qkv);
    cudaGetSymbolAddress((void**)&pAh,  g_ah);
    cudaGetSymbolAddress((void**)&pAl,  g_al);
    cudaGetSymbolAddress((void**)&pBh,  g_bh);
    cudaGetSymbolAddress((void**)&pBl,  g_bl);
    cudaGetSymbolAddress((void**)&pWh,  g_wh);
    cudaGetSymbolAddress((void**)&pWl,  g_wl);
    cudaGetSymbolAddress((void**)&pPart, g_part);

    cudaFuncSetAttribute(mma_gemm<0>, cudaFuncAttributeMaxDynamicSharedMemorySize, SMEM_GEMM);
    cudaFuncSetAttribute(mma_gemm<1>, cudaFuncAttributeMaxDynamicSharedMemorySize, SMEM_GEMM);
    cudaFuncSetAttribute(mma_gemm<4>, cudaFuncAttributeMaxDynamicSharedMemorySize, SMEM_GEMM);
    cudaFuncSetAttribute(mma_gemm<5>, cudaFuncAttributeMaxDynamicSharedMemorySize, SMEM_GEMM);
    cudaFuncSetAttribute(head_gemm, cudaFuncAttributeMaxDynamicSharedMemorySize, SMEM_HEAD);

    const size_t LWB = (size_t)6 * D_ * D_;
    const dim3 gQKV(24, 98);
    const dim3 gStd(8, 98);

    convAll<<<12 * 1024, 256>>>(wq, wk, wv, wo, w1, w2, pWh, pWl);
    embed_kernel<<<dim3(D_ / 64, B_), 256>>>(x, pos);

    for (int i = 0; i < L_; i++) {
        const __nv_bfloat16* Wh = pWh + i * LWB;
        const __nv_bfloat16* Wl = pWl + i * LWB;
        ln_split_kernel<<<M_, 256>>>(pH, pAh, pAl, ln1_s + i * D_, ln1_b + i * D_);
        mma_gemm<0><<<gQKV, 256, SMEM_GEMM>>>(pAh, pAl, Wh, Wl, nullptr, nullptr, pQKV,
                                              D_, 3072, 32, 3072, nullptr, nullptr);
        attn_kernel<<<B_ * H_, 256>>>();
        mma_gemm<1><<<gStd, 256, SMEM_GEMM>>>(pAh, pAl, Wh + 3 * (size_t)D_ * D_, Wl + 3 * (size_t)D_ * D_,
                                              nullptr, pH, pH, D_, 1024, 32, 1024, nullptr, nullptr);
        ln_split_kernel<<<M_, 256>>>(pH, pAh, pAl, ln2_s + i * D_, ln2_b + i * D_);
        mma_gemm<5><<<gStd, 256, SMEM_GEMM>>>(pAh, pAl, Wh + 4 * (size_t)D_ * D_, Wl + 4 * (size_t)D_ * D_,
                                              b1 + i * FF_, nullptr, nullptr, D_, 1024, 32, 1024, pBh, pBl);
        mma_gemm<4><<<gStd, 256, SMEM_GEMM>>>(pBh, pBl, Wh + 5 * (size_t)D_ * D_, Wl + 5 * (size_t)D_ * D_,
                                              b2 + i * D_, pH, pH, FF_, 1024, 32, 1024, nullptr, nullptr);
    }

    ln_split_kernel<<<M_, 256>>>(pH, pAh, pAl, lnf_s, lnf_b);

    // head: encoder-shaped tiles, 2 CTAs/SM, split-K = 16
    head_gemm<<<dim3(8, 2, 16), 256, SMEM_HEAD>>>(pAh, pAl, head_w, pPart);
    head_reduce<<<B_ * OUT_ / 256, 256>>>(pPart, head_b, out);
}

// round 14
// speedup vs baseline: 1.0119x; 1.0119x over previous
#include <cuda_runtime.h>
#include <cuda_bf16.h>
#include <math.h>
#include <cstdint>

// ---------------- problem constants ----------------
#define B_    256
#define C_    1024
#define S_    49
#define D_    1024
#define L_    2
#define H_    2
#define HD_   512
#define FF_   1024
#define OUT_  1024
#define M_    (B_ * S_)   // 12544 rows
#define KHEAD (S_ * D_)   // 50176

// ---------------- device scratch (no allocs allowed) ----------------
__device__ float g_h  [M_ * D_];
__device__ float g_qkv[M_ * 3 * D_];
__device__ __nv_bfloat16 g_ah[M_ * D_];
__device__ __nv_bfloat16 g_al[M_ * D_];
__device__ __nv_bfloat16 g_bh[M_ * FF_];
__device__ __nv_bfloat16 g_bl[M_ * FF_];
__device__ __nv_bfloat16 g_wh[L_ * 6 * D_ * D_];
__device__ __nv_bfloat16 g_wl[L_ * 6 * D_ * D_];
__device__ float g_part[16 * B_ * OUT_];

// ---------------- helpers ----------------
__device__ __forceinline__ float gelu_new(float x) {
    float x3 = x * x * x;
    return 0.5f * x * (1.f + tanhf(0.7978845608028654f * (x + 0.044715f * x3)));
}
__device__ __forceinline__ void split2(float v, __nv_bfloat16& h, __nv_bfloat16& l) {
    h = __float2bfloat16(v);
    l = __float2bfloat16(v - __bfloat162float(h));
}

__device__ __forceinline__ void mma16816(float* d, const uint32_t* a, const uint32_t* b) {
    asm volatile(
        "mma.sync.aligned.m16n8k16.row.col.f32.bf16.bf16.f32 "
        "{%0,%1,%2,%3}, {%4,%5,%6,%7}, {%8,%9}, {%0,%1,%2,%3};"
        : "+f"(d[0]), "+f"(d[1]), "+f"(d[2]), "+f"(d[3])
        : "r"(a[0]), "r"(a[1]), "r"(a[2]), "r"(a[3]), "r"(b[0]), "r"(b[1]));
}
__device__ __forceinline__ void ldm4(uint32_t* r, uint32_t addr) {
    asm volatile("ldmatrix.sync.aligned.m8n8.x4.shared.b16 {%0,%1,%2,%3}, [%4];"
                 : "=r"(r[0]), "=r"(r[1]), "=r"(r[2]), "=r"(r[3]) : "r"(addr));
}
__device__ __forceinline__ void ldm4t(uint32_t* r, uint32_t addr) {
    asm volatile("ldmatrix.sync.aligned.m8n8.x4.trans.shared.b16 {%0,%1,%2,%3}, [%4];"
                 : "=r"(r[0]), "=r"(r[1]), "=r"(r[2]), "=r"(r[3]) : "r"(addr));
}

// ================= mma.sync bf16 split GEMM (round-12, unchanged) =================
#define PADA   80
#define PADB2  272
#define A128   (128 * PADA)            // 10240 per matrix
#define BMAT   (32 * PADB2)            // 8704
#define BOFF   (2 * A128)              // 20480
#define STAGEB (2 * A128 + 2 * BMAT)   // 37888
#define SMEM_GEMM (3 * STAGEB)         // 113664

template<int EPI>
__global__ __launch_bounds__(256, 2) void mma_gemm(
    const __nv_bfloat16* __restrict__ Ah, const __nv_bfloat16* __restrict__ Al,
    const __nv_bfloat16* __restrict__ Bh, const __nv_bfloat16* __restrict__ Bl,
    const float* __restrict__ bias, const float* __restrict__ R, float* __restrict__ C,
    int ld, int ldb, int kIters, int ldc,
    __nv_bfloat16* __restrict__ Ch, __nv_bfloat16* __restrict__ Cl)
{
    extern __shared__ char smem[];
    uint32_t sm0;
    asm("{ .reg .u64 t; cvta.to.shared.u64 t, %1; cvt.u32.u64 %0, t; }" : "=r"(sm0) : "l"(smem));
    int tid = threadIdx.x, wid = tid >> 5, lane = tid & 31;
    int bn = blockIdx.x, bm = blockIdx.y;

    const __nv_bfloat16* srcs[8];
    uint32_t dsts[8];
#pragma unroll
    for (int j = 0; j < 8; j++) {
        int slot = tid + j * 256;
        if (j < 4) {
            int mat = slot >> 9;
            int r   = (slot >> 2) & 127;
            int sg  = slot & 3;
            const __nv_bfloat16* base = mat ? Al : Ah;
            srcs[j] = base + (size_t)(bm * 128 + r) * ld + sg * 8;
            dsts[j] = sm0 + mat * A128 + r * PADA + sg * 16;
        } else {
            int s2  = slot - 1024;
            int mat = s2 >> 9;
            int r   = (s2 >> 4) & 31;
            int sg  = s2 & 15;
            const __nv_bfloat16* base = mat ? Bl : Bh;
            srcs[j] = base + (size_t)r * ldb + bn * 128 + sg * 8;
            dsts[j] = sm0 + BOFF + mat * BMAT + r * PADB2 + sg * 16;
        }
    }

#define LOAD_STAGE(stg)                                                            \
    {                                                                              \
        _Pragma("unroll")                                                          \
        for (int j = 0; j < 8; j++) {                                              \
            asm volatile("cp.async.cg.shared.global [%0], [%1], 16;"               \
                         :: "r"(dsts[j] + (stg) * STAGEB), "l"(srcs[j]) : "memory"); \
            srcs[j] += (j < 4) ? 32 : (size_t)32 * ldb;                            \
        }                                                                          \
        asm volatile("cp.async.commit_group;" ::: "memory");                       \
    }

    int warp_m = wid >> 2, warp_n = wid & 3;
    int g = lane >> 2, tg = lane & 3;
    int t8 = lane >> 3, tl = lane & 7;
    uint32_t aBase = (uint32_t)((warp_m * 64 + (t8 & 1) * 8 + tl) * PADA + (t8 >> 1) * 16);
    uint32_t bBase = (uint32_t)(((t8 & 1) * 8 + tl) * PADB2 + (warp_n * 32 + (t8 >> 1) * 8) * 2);

    float acc[4][4][4];
#pragma unroll
    for (int mt = 0; mt < 4; mt++)
#pragma unroll
        for (int nt = 0; nt < 4; nt++)
#pragma unroll
            for (int j = 0; j < 4; j++) acc[mt][nt][j] = 0.f;

    LOAD_STAGE(0);
    LOAD_STAGE(1);

    for (int it = 0; it < kIters; it++) {
        asm volatile("cp.async.wait_group 1;" ::: "memory");
        __syncthreads();
        uint32_t st = sm0 + (it % 3) * STAGEB;

#pragma unroll
        for (int ks = 0; ks < 2; ks++) {
            uint32_t bh[4][2], bl[4][2];
#pragma unroll
            for (int p = 0; p < 2; p++) {
                uint32_t rb = st + BOFF + bBase + ks * (16 * PADB2) + p * 32;
                uint32_t r4[4];
                ldm4t(r4, rb);
                bh[2 * p][0] = r4[0]; bh[2 * p][1] = r4[1];
                bh[2 * p + 1][0] = r4[2]; bh[2 * p + 1][1] = r4[3];
                ldm4t(r4, rb + BMAT);
                bl[2 * p][0] = r4[0]; bl[2 * p][1] = r4[1];
                bl[2 * p + 1][0] = r4[2]; bl[2 * p + 1][1] = r4[3];
            }
#pragma unroll
            for (int mt = 0; mt < 4; mt++) {
                uint32_t ra = st + aBase + mt * (16 * PADA) + ks * 32;
                uint32_t ah[4], al[4];
                ldm4(ah, ra);
                ldm4(al, ra + A128);
#pragma unroll
                for (int nt = 0; nt < 4; nt++) {
                    mma16816(acc[mt][nt], ah, bh[nt]);
                    mma16816(acc[mt][nt], ah, bl[nt]);
                    mma16816(acc[mt][nt], al, bh[nt]);
                }
            }
        }
        if (it + 2 < kIters) {
            LOAD_STAGE((it + 2) % 3);
        } else {
            asm volatile("cp.async.commit_group;" ::: "memory");
        }
    }

#pragma unroll
    for (int mt = 0; mt < 4; mt++) {
        int row0 = bm * 128 + warp_m * 64 + mt * 16 + g;
#pragma unroll
        for (int nt = 0; nt < 4; nt++) {
            int col = bn * 128 + warp_n * 32 + nt * 8 + tg * 2;
#pragma unroll
            for (int half = 0; half < 2; half++) {
                int row = row0 + half * 8;
                float2 v = make_float2(acc[mt][nt][half * 2], acc[mt][nt][half * 2 + 1]);
                if (EPI == 1) {
                    const float2 r = *(const float2*)(R + (size_t)row * ldc + col);
                    v.x += r.x; v.y += r.y;
                }
                if (EPI == 4) {
                    const float2 b = *(const float2*)(bias + col);
                    const float2 r = *(const float2*)(R + (size_t)row * ldc + col);
                    v.x += b.x + r.x; v.y += b.y + r.y;
                }
                if (EPI == 5) {
                    const float2 b = *(const float2*)(bias + col);
                    v.x = gelu_new(v.x + b.x); v.y = gelu_new(v.y + b.y);
                    __nv_bfloat162 hh, ll;
                    split2(v.x, hh.x, ll.x);
                    split2(v.y, hh.y, ll.y);
                    *(__nv_bfloat162*)(Ch + (size_t)row * ldc + col) = hh;
                    *(__nv_bfloat162*)(Cl + (size_t)row * ldc + col) = ll;
                } else {
                    *(float2*)(C + (size_t)row * ldc + col) = v;
                }
            }
        }
    }
#undef LOAD_STAGE
}

// ================= head GEMM (round-12 version: 256-row tile, one sync/iter, W read once) =================
#define HPADA  80
#define HAMAT  (256 * HPADA)                   // 20480
#define HA_STAGE (2 * HAMAT)                   // 40960
#define HB_BUF   (2 * BMAT)                    // 17408
#define HB_OFF   (3 * HA_STAGE)                // 122880
#define SMEM_HEAD (HB_OFF + 2 * HB_BUF)        // 157696
#define HK_ITERS 98

__global__ __launch_bounds__(256, 1) void head_gemm(
    const __nv_bfloat16* __restrict__ Ah, const __nv_bfloat16* __restrict__ Al,
    const float* __restrict__ W, float* __restrict__ Cpart)
{
    extern __shared__ char smem[];
    uint32_t sm0;
    asm("{ .reg .u64 t; cvta.to.shared.u64 t, %1; cvt.u32.u64 %0, t; }" : "=r"(sm0) : "l"(smem));
    int tid = threadIdx.x, wid = tid >> 5, lane = tid & 31;
    int bn = blockIdx.x, bz = blockIdx.z;
    size_t kStart = (size_t)bz * HK_ITERS * 32;

    const __nv_bfloat16* asrc[8];
    uint32_t adst[8];
#pragma unroll
    for (int j = 0; j < 8; j++) {
        int slot = tid + j * 256;
        int mat = slot >> 10;
        int r   = (slot >> 2) & 255;
        int sg  = slot & 3;
        const __nv_bfloat16* base = mat ? Al : Ah;
        asrc[j] = base + (size_t)r * KHEAD + kStart + sg * 8;
        adst[j] = sm0 + mat * HAMAT + r * HPADA + sg * 16;
    }
#define LOADA(stg)                                                                \
    {                                                                             \
        _Pragma("unroll")                                                         \
        for (int j = 0; j < 8; j++) {                                             \
            asm volatile("cp.async.cg.shared.global [%0], [%1], 16;"              \
                         :: "r"(adst[j] + (stg) * HA_STAGE), "l"(asrc[j]) : "memory"); \
            asrc[j] += 32;                                                        \
        }                                                                         \
        asm volatile("cp.async.commit_group;" ::: "memory");                      \
    }

    int brow = tid >> 3, bseg = tid & 7;
    const float* bsrc = W + (kStart + brow) * 1024 + bn * 128 + bseg * 16;
    uint32_t bsm = sm0 + HB_OFF + brow * PADB2 + bseg * 32;

    int warp_m = wid >> 1, warp_n = wid & 1;
    int g = lane >> 2, tg = lane & 3;
    int t8 = lane >> 3, tl = lane & 7;
    uint32_t aBase = (uint32_t)((warp_m * 64 + (t8 & 1) * 8 + tl) * HPADA + (t8 >> 1) * 16);
    uint32_t bBase = (uint32_t)(((t8 & 1) * 8 + tl) * PADB2 + (warp_n * 64 + (t8 >> 1) * 8) * 2);

    float acc[4][8][4];
#pragma unroll
    for (int mt = 0; mt < 4; mt++)
#pragma unroll
        for (int nt = 0; nt < 8; nt++)
#pragma unroll
            for (int j = 0; j < 4; j++) acc[mt][nt][j] = 0.f;

    LOADA(0);
    LOADA(1);
    float4 br[4];
#pragma unroll
    for (int i = 0; i < 4; i++) br[i] = *(const float4*)(bsrc + i * 4);

    for (int it = 0; it < HK_ITERS; it++) {
        uint32_t bd = bsm + (it & 1) * HB_BUF;
#pragma unroll
        for (int i = 0; i < 4; i++) {
            __nv_bfloat162 h0, h1, l0, l1;
            split2(br[i].x, h0.x, l0.x); split2(br[i].y, h0.y, l0.y);
            split2(br[i].z, h1.x, l1.x); split2(br[i].w, h1.y, l1.y);
            uint32_t hvx = *(uint32_t*)&h0, hvy = *(uint32_t*)&h1;
            uint32_t lvx = *(uint32_t*)&l0, lvy = *(uint32_t*)&l1;
            asm volatile("st.shared.v2.u32 [%0], {%1, %2};" :: "r"(bd + i * 8), "r"(hvx), "r"(hvy) : "memory");
            asm volatile("st.shared.v2.u32 [%0], {%1, %2};" :: "r"(bd + BMAT + i * 8), "r"(lvx), "r"(lvy) : "memory");
        }
        if (it + 1 < HK_ITERS) {
            const float* nb = bsrc + (size_t)(it + 1) * 32 * 1024;
#pragma unroll
            for (int i = 0; i < 4; i++) br[i] = *(const float4*)(nb + i * 4);
        }
        asm volatile("cp.async.wait_group 1;" ::: "memory");
        __syncthreads();

        uint32_t st = sm0 + (it % 3) * HA_STAGE;
        uint32_t bb = sm0 + HB_OFF + (it & 1) * HB_BUF;
#pragma unroll
        for (int ks = 0; ks < 2; ks++) {
            uint32_t bh[8][2], bl[8][2];
#pragma unroll
            for (int p = 0; p < 4; p++) {
                uint32_t rb = bb + bBase + ks * (16 * PADB2) + p * 32;
                uint32_t r4[4];
                ldm4t(r4, rb);
                bh[2 * p][0] = r4[0]; bh[2 * p][1] = r4[1];
                bh[2 * p + 1][0] = r4[2]; bh[2 * p + 1][1] = r4[3];
                ldm4t(r4, rb + BMAT);
                bl[2 * p][0] = r4[0]; bl[2 * p][1] = r4[1];
                bl[2 * p + 1][0] = r4[2]; bl[2 * p + 1][1] = r4[3];
            }
#pragma unroll
            for (int mt = 0; mt < 4; mt++) {
                uint32_t ra = st + aBase + mt * (16 * HPADA) + ks * 32;
                uint32_t ah[4], al[4];
                ldm4(ah, ra);
                ldm4(al, ra + HAMAT);
#pragma unroll
                for (int nt = 0; nt < 8; nt++) {
                    mma16816(acc[mt][nt], ah, bh[nt]);
                    mma16816(acc[mt][nt], ah, bl[nt]);
                    mma16816(acc[mt][nt], al, bh[nt]);
                }
            }
        }
        if (it + 2 < HK_ITERS) {
            LOADA((it + 2) % 3);
        } else {
            asm volatile("cp.async.commit_group;" ::: "memory");
        }
    }

    float* Cp = Cpart + (size_t)bz * (B_ * OUT_);
#pragma unroll
    for (int mt = 0; mt < 4; mt++) {
        int row0 = warp_m * 64 + mt * 16 + g;
#pragma unroll
        for (int nt = 0; nt < 8; nt++) {
            int col = bn * 128 + warp_n * 64 + nt * 8 + tg * 2;
#pragma unroll
            for (int half = 0; half < 2; half++) {
                int row = row0 + half * 8;
                *(float2*)(Cp + (size_t)row * 1024 + col) =
                    make_float2(acc[mt][nt][half * 2], acc[mt][nt][half * 2 + 1]);
            }
        }
    }
#undef LOADA
}

// ---------------- merged weight conversion ----------------
__global__ void convAll(const float* __restrict__ wq, const float* __restrict__ wk,
                        const float* __restrict__ wv, const float* __restrict__ wo,
                        const float* __restrict__ w1, const float* __restrict__ w2,
                        __nv_bfloat16* __restrict__ Wh, __nv_bfloat16* __restrict__ Wl) {
    int unit = blockIdx.x >> 10;
    int blk  = blockIdx.x & 1023;
    int layer = unit / 6, widx = unit % 6;
    const float* srcs[6] = {wq, wk, wv, wo, w1, w2};
    const float* src = srcs[widx] + (size_t)layer * D_ * D_;
    size_t idx = (size_t)blk * 1024 + threadIdx.x * 4;
    int k = (int)(idx >> 10);
    int n = (int)(idx & 1023);
    int Nout  = (widx < 3) ? 3072 : 1024;
    int coloff = (widx < 3) ? widx * 1024 : 0;
    size_t dbase = (size_t)layer * 6 * D_ * D_ + ((widx < 3) ? 0 : (size_t)widx * D_ * D_);
    size_t o = dbase + (size_t)k * Nout + coloff + n;
    float4 v = *(const float4*)(src + idx);
    __nv_bfloat162 h0, h1, l0, l1;
    split2(v.x, h0.x, l0.x); split2(v.y, h0.y, l0.y);
    split2(v.z, h1.x, l1.x); split2(v.w, h1.y, l1.y);
    *(__nv_bfloat162*)(Wh + o) = h0;
    *(__nv_bfloat162*)(Wh + o + 2) = h1;
    *(__nv_bfloat162*)(Wl + o) = l0;
    *(__nv_bfloat162*)(Wl + o + 2) = l1;
}

// ---------------- head reduce ----------------
__global__ void head_reduce(const float* __restrict__ parts, const float* __restrict__ bias,
                            float* __restrict__ out) {
    int i = blockIdx.x * blockDim.x + threadIdx.x;
    float s = bias[i & (OUT_ - 1)];
#pragma unroll
    for (int z = 0; z < 16; z++) s += parts[(size_t)z * (B_ * OUT_) + i];
    out[i] = fmaxf(s, 0.f);
}

// ---------------- embed ----------------
__global__ void embed_kernel(const float* __restrict__ x, const float* __restrict__ pos) {
    __shared__ float tile[64][S_ + 1];
    int b = blockIdx.y;
    int d0 = blockIdx.x * 64;
    int tid = threadIdx.x;
    for (int idx = tid; idx < 64 * S_; idx += 256) {
        int dr = idx / S_, s = idx % S_;
        tile[dr][s] = x[(size_t)(b * C_ + d0 + dr) * S_ + s];
    }
    __syncthreads();
    for (int idx = tid; idx < S_ * 64; idx += 256) {
        int s = idx >> 6, dr = idx & 63;
        g_h[(size_t)(b * S_ + s) * D_ + d0 + dr] = tile[dr][s] + pos[s * D_ + d0 + dr];
    }
}

// ---------------- layernorm (vectorized) ----------------
__global__ void ln_split_kernel(const float* __restrict__ in,
                                __nv_bfloat16* __restrict__ oh, __nv_bfloat16* __restrict__ ol,
                                const float* __restrict__ sc, const float* __restrict__ bi) {
    int row = blockIdx.x;
    int tid = threadIdx.x;
    int d0 = tid * 4;
    float4 v = *(const float4*)(in + (size_t)row * D_ + d0);
    float s = v.x + v.y + v.z + v.w;
    float ss = v.x * v.x + v.y * v.y + v.z * v.z + v.w * v.w;

    __shared__ float rs[8], rss[8];
    int lane = tid & 31, w = tid >> 5;
#pragma unroll
    for (int o = 16; o; o >>= 1) {
        s  += __shfl_xor_sync(0xffffffffu, s,  o);
        ss += __shfl_xor_sync(0xffffffffu, ss, o);
    }
    if (lane == 0) { rs[w] = s; rss[w] = ss; }
    __syncthreads();
    if (tid < 32) {
        float s2  = (tid < 8) ? rs[tid]  : 0.f;
        float ss2 = (tid < 8) ? rss[tid] : 0.f;
#pragma unroll
        for (int o = 4; o; o >>= 1) {
            s2  += __shfl_xor_sync(0xffffffffu, s2,  o);
            ss2 += __shfl_xor_sync(0xffffffffu, ss2, o);
        }
        if (tid == 0) { rs[0] = s2; rss[0] = ss2; }
    }
    __syncthreads();
    float mean = rs[0] * (1.f / 1024.f);
    float var  = rss[0] * (1.f / 1024.f) - mean * mean;
    float inv  = rsqrtf(var + 1e-5f);

    float4 scv = *(const float4*)(sc + d0);
    float4 biv = *(const float4*)(bi + d0);
    float r0 = (v.x - mean) * inv * scv.x + biv.x;
    float r1 = (v.y - mean) * inv * scv.y + biv.y;
    float r2 = (v.z - mean) * inv * scv.z + biv.z;
    float r3 = (v.w - mean) * inv * scv.w + biv.w;
    __nv_bfloat162 h0, h1, l0, l1;
    split2(r0, h0.x, l0.x); split2(r1, h0.y, l0.y);
    split2(r2, h1.x, l1.x); split2(r3, h1.y, l1.y);
    uint2 hv, lv;
    hv.x = *(uint32_t*)&h0; hv.y = *(uint32_t*)&h1;
    lv.x = *(uint32_t*)&l0; lv.y = *(uint32_t*)&l1;
    *(uint2*)(oh + (size_t)row * D_ + d0) = hv;
    *(uint2*)(ol + (size_t)row * D_ + d0) = lv;
}

// ---------------- fused attention: 4x4 register blocking ----------------
__global__ void attn_kernel() {
    int bh = blockIdx.x;
    int b  = bh >> 1;
    int hh = bh & 1;
    __shared__ float qs[52 * 65];
    __shared__ float ks[52 * 65];
    __shared__ float sc[52 * 50];
    int tid = threadIdx.x;
    const size_t baseQ = (size_t)b * S_ * 3072 + hh * HD_;

    for (int idx = tid; idx < 3 * 65; idx += 256) {
        qs[49 * 65 + idx] = 0.f;
        ks[49 * 65 + idx] = 0.f;
    }
    for (int idx = tid; idx < 3 * 50; idx += 256) sc[49 * 50 + idx] = 0.f;

    int tq = tid / 13, tk = tid - tq * 13;
    bool p1 = (tid < 169);
    int q0 = tq * 4, k0 = tk * 4;
    float acc[4][4];
#pragma unroll
    for (int i = 0; i < 4; i++)
#pragma unroll
        for (int j = 0; j < 4; j++) acc[i][j] = 0.f;

    for (int c = 0; c < 8; c++) {
        __syncthreads();
        for (int idx = tid; idx < S_ * 16; idx += 256) {
            int r = idx >> 4, f = idx & 15;
            const float* gp = g_qkv + baseQ + (size_t)r * 3072 + c * 64 + f * 4;
            float4 qv = *(const float4*)gp;
            float4 kv = *(const float4*)(gp + 1024);
            float* qd = &qs[r * 65 + f * 4];
            float* kd = &ks[r * 65 + f * 4];
            qd[0] = qv.x; qd[1] = qv.y; qd[2] = qv.z; qd[3] = qv.w;
            kd[0] = kv.x; kd[1] = kv.y; kd[2] = kv.z; kd[3] = kv.w;
        }
        __syncthreads();
        if (p1) {
#pragma unroll 4
            for (int d = 0; d < 64; d++) {
                float ra[4], rb[4];
#pragma unroll
                for (int i = 0; i < 4; i++) {
                    ra[i] = qs[(q0 + i) * 65 + d];
                    rb[i] = ks[(k0 + i) * 65 + d];
                }
#pragma unroll
                for (int i = 0; i < 4; i++)
#pragma unroll
                    for (int j = 0; j < 4; j++) acc[i][j] += ra[i] * rb[j];
            }
        }
    }
    __syncthreads();
    const float scale = 0.044194173824159216f;
    if (p1) {
#pragma unroll
        for (int i = 0; i < 4; i++)
#pragma unroll
            for (int j = 0; j < 4; j++) {
                int q = q0 + i, k = k0 + j;
                if (q < S_ && k < S_) sc[q * 50 + k] = acc[i][j] * scale;
            }
    }
    __syncthreads();

    if (tid < S_) {
        float mx = -1e30f;
        for (int k = 0; k < S_; k++) mx = fmaxf(mx, sc[tid * 50 + k]);
        float sum = 0.f;
        for (int k = 0; k < S_; k++) {
            float e = __expf(sc[tid * 50 + k] - mx);
            sc[tid * 50 + k] = e; sum += e;
        }
        float inv = 1.f / sum;
        for (int k = 0; k < S_; k++) sc[tid * 50 + k] *= inv;
    }

    int tq2 = tid >> 4, td = tid & 15;
    bool p2 = (tq2 < 13);
    int q2 = tq2 * 4, d0 = td * 4;
    const size_t baseO = (size_t)b * S_ * D_ + hh * HD_;

    for (int c = 0; c < 8; c++) {
        __syncthreads();
        for (int idx = tid; idx < S_ * 16; idx += 256) {
            int r = idx >> 4, f = idx & 15;
            float4 vv = *(const float4*)(g_qkv + baseQ + 2048 + (size_t)r * 3072 + c * 64 + f * 4);
            float* vd = &ks[r * 65 + f * 4];
            vd[0] = vv.x; vd[1] = vv.y; vd[2] = vv.z; vd[3] = vv.w;
        }
        __syncthreads();
        if (p2) {
            float a2[4][4];
#pragma unroll
            for (int i = 0; i < 4; i++)
#pragma unroll
                for (int j = 0; j < 4; j++) a2[i][j] = 0.f;
            for (int k = 0; k < S_; k++) {
                float ra[4], rb[4];
#pragma unroll
                for (int i = 0; i < 4; i++) ra[i] = sc[(q2 + i) * 50 + k];
#pragma unroll
                for (int j = 0; j < 4; j++) rb[j] = ks[k * 65 + d0 + j];
#pragma unroll
                for (int i = 0; i < 4; i++)
#pragma unroll
                    for (int j = 0; j < 4; j++) a2[i][j] += ra[i] * rb[j];
            }
#pragma unroll
            for (int i = 0; i < 4; i++) {
                int q = q2 + i;
                if (q < S_) {
                    size_t o = baseO + (size_t)q * D_ + c * 64 + d0;
                    __nv_bfloat162 h0, h1, l0, l1;
                    split2(a2[i][0], h0.x, l0.x);
                    split2(a2[i][1], h0.y, l0.y);
                    split2(a2[i][2], h1.x, l1.x);
                    split2(a2[i][3], h1.y, l1.y);
                    uint2 hv, lv;
                    hv.x = *(uint32_t*)&h0; hv.y = *(uint32_t*)&h1;
                    lv.x = *(uint32_t*)&l0; lv.y = *(uint32_t*)&l1;
                    *(uint2*)(g_ah + o) = hv;
                    *(uint2*)(g_al + o) = lv;
                }
            }
        }
    }
}

// ---------------- host orchestration ----------------
extern "C" void kernel_launch(void* const* d_in, const int* in_sizes, int n_in,
                              void* d_out, int out_size) {
    (void)in_sizes; (void)n_in; (void)out_size;
    const float* x      = (const float*)d_in[0];
    const float* pos    = (const float*)d_in[1];
    const float* ln1_s  = (const float*)d_in[2];
    const float* ln1_b  = (const float*)d_in[3];
    const float* wq     = (const float*)d_in[4];
    const float* wk     = (const float*)d_in[5];
    const float* wv     = (const float*)d_in[6];
    const float* wo     = (const float*)d_in[7];
    const float* ln2_s  = (const float*)d_in[8];
    const float* ln2_b  = (const float*)d_in[9];
    const float* w1     = (const float*)d_in[10];
    const float* b1     = (const float*)d_in[11];
    const float* w2     = (const float*)d_in[12];
    const float* b2     = (const float*)d_in[13];
    const float* lnf_s  = (const float*)d_in[14];
    const float* lnf_b  = (const float*)d_in[15];
    const float* head_w = (const float*)d_in[16];
    const float* head_b = (const float*)d_in[17];
    float* out = (float*)d_out;

    float *pH, *pQKV, *pPart;
    __nv_bfloat16 *pAh, *pAl, *pBh, *pBl, *pWh, *pWl;
    cudaGetSymbolAddress((void**)&pH,   g_h);
    cudaGetSymbolAddress((void**)&pQKV, g_qkv);
    cudaGetSymbolAddress((void**)&pAh,  g_ah);
    cudaGetSymbolAddress((void**)&pAl,  g_al);
    cudaGetSymbolAddress((void**)&pBh,  g_bh);
    cudaGetSymbolAddress((void**)&pBl,  g_bl);
    cudaGetSymbolAddress((void**)&pWh,  g_wh);
    cudaGetSymbolAddress((void**)&pWl,  g_wl);
    cudaGetSymbolAddress((void**)&pPart, g_part);

    cudaFuncSetAttribute(mma_gemm<0>, cudaFuncAttributeMaxDynamicSharedMemorySize, SMEM_GEMM);
    cudaFuncSetAttribute(mma_gemm<1>, cudaFuncAttributeMaxDynamicSharedMemorySize, SMEM_GEMM);
    cudaFuncSetAttribute(mma_gemm<4>, cudaFuncAttributeMaxDynamicSharedMemorySize, SMEM_GEMM);
    cudaFuncSetAttribute(mma_gemm<5>, cudaFuncAttributeMaxDynamicSharedMemorySize, SMEM_GEMM);
    cudaFuncSetAttribute(head_gemm, cudaFuncAttributeMaxDynamicSharedMemorySize, SMEM_HEAD);

    const size_t LWB = (size_t)6 * D_ * D_;
    const dim3 gQKV(24, 98);
    const dim3 gStd(8, 98);

    convAll<<<12 * 1024, 256>>>(wq, wk, wv, wo, w1, w2, pWh, pWl);
    embed_kernel<<<dim3(D_ / 64, B_), 256>>>(x, pos);

    for (int i = 0; i < L_; i++) {
        const __nv_bfloat16* Wh = pWh + i * LWB;
        const __nv_bfloat16* Wl = pWl + i * LWB;
        ln_split_kernel<<<M_, 256>>>(pH, pAh, pAl, ln1_s + i * D_, ln1_b + i * D_);
        mma_gemm<0><<<gQKV, 256, SMEM_GEMM>>>(pAh, pAl, Wh, Wl, nullptr, nullptr, pQKV,
                                              D_, 3072, 32, 3072, nullptr, nullptr);
        attn_kernel<<<B_ * H_, 256>>>();
        mma_gemm<1><<<gStd, 256, SMEM_GEMM>>>(pAh, pAl, Wh + 3 * (size_t)D_ * D_, Wl + 3 * (size_t)D_ * D_,
                                              nullptr, pH, pH, D_, 1024, 32, 1024, nullptr, nullptr);
        ln_split_kernel<<<M_, 256>>>(pH, pAh, pAl, ln2_s + i * D_, ln2_b + i * D_);
        mma_gemm<5><<<gStd, 256, SMEM_GEMM>>>(pAh, pAl, Wh + 4 * (size_t)D_ * D_, Wl + 4 * (size_t)D_ * D_,
                                              b1 + i * FF_, nullptr, nullptr, D_, 1024, 32, 1024, pBh, pBl);
        mma_gemm<4><<<gStd, 256, SMEM_GEMM>>>(pBh, pBl, Wh + 5 * (size_t)D_ * D_, Wl + 5 * (size_t)D_ * D_,
                                              b2 + i * D_, pH, pH, FF_, 1024, 32, 1024, nullptr, nullptr);
    }

    ln_split_kernel<<<M_, 256>>>(pH, pAh, pAl, lnf_s, lnf_b);

    // head: 256-row tile, W read once, split-K = 16
    head_gemm<<<dim3(8, 1, 16), 256, SMEM_HEAD>>>(pAh, pAl, head_w, pPart);
    head_reduce<<<B_ * OUT_ / 256, 256>>>(pPart, head_b, out);
}

// round 15
// speedup vs baseline: 1.0202x; 1.0082x over previous
#include <cuda_runtime.h>
#include <cuda_bf16.h>
#include <math.h>
#include <cstdint>

// ---------------- problem constants ----------------
#define B_    256
#define C_    1024
#define S_    49
#define D_    1024
#define L_    2
#define H_    2
#define HD_   512
#define FF_   1024
#define OUT_  1024
#define M_    (B_ * S_)   // 12544 rows
#define KHEAD (S_ * D_)   // 50176
#define KSPLIT 37          // head split-K: 8*37 = 296 CTAs = 2/SM exactly

// ---------------- device scratch (no allocs allowed) ----------------
__device__ float g_h  [M_ * D_];
__device__ float g_qkv[M_ * 3 * D_];
__device__ __nv_bfloat16 g_ah[M_ * D_];
__device__ __nv_bfloat16 g_al[M_ * D_];
__device__ __nv_bfloat16 g_bh[M_ * FF_];
__device__ __nv_bfloat16 g_bl[M_ * FF_];
__device__ __nv_bfloat16 g_wh[L_ * 6 * D_ * D_];
__device__ __nv_bfloat16 g_wl[L_ * 6 * D_ * D_];
__device__ float g_part[KSPLIT * B_ * OUT_];

// ---------------- helpers ----------------
__device__ __forceinline__ float gelu_new(float x) {
    float x3 = x * x * x;
    return 0.5f * x * (1.f + tanhf(0.7978845608028654f * (x + 0.044715f * x3)));
}
__device__ __forceinline__ void split2(float v, __nv_bfloat16& h, __nv_bfloat16& l) {
    h = __float2bfloat16(v);
    l = __float2bfloat16(v - __bfloat162float(h));
}

__device__ __forceinline__ void mma16816(float* d, const uint32_t* a, const uint32_t* b) {
    asm volatile(
        "mma.sync.aligned.m16n8k16.row.col.f32.bf16.bf16.f32 "
        "{%0,%1,%2,%3}, {%4,%5,%6,%7}, {%8,%9}, {%0,%1,%2,%3};"
        : "+f"(d[0]), "+f"(d[1]), "+f"(d[2]), "+f"(d[3])
        : "r"(a[0]), "r"(a[1]), "r"(a[2]), "r"(a[3]), "r"(b[0]), "r"(b[1]));
}
__device__ __forceinline__ void ldm4(uint32_t* r, uint32_t addr) {
    asm volatile("ldmatrix.sync.aligned.m8n8.x4.shared.b16 {%0,%1,%2,%3}, [%4];"
                 : "=r"(r[0]), "=r"(r[1]), "=r"(r[2]), "=r"(r[3]) : "r"(addr));
}
__device__ __forceinline__ void ldm4t(uint32_t* r, uint32_t addr) {
    asm volatile("ldmatrix.sync.aligned.m8n8.x4.trans.shared.b16 {%0,%1,%2,%3}, [%4];"
                 : "=r"(r[0]), "=r"(r[1]), "=r"(r[2]), "=r"(r[3]) : "r"(addr));
}

// ================= mma.sync bf16 split GEMM (round-12, unchanged) =================
#define PADA   80
#define PADB2  272
#define A128   (128 * PADA)            // 10240 per matrix
#define BMAT   (32 * PADB2)            // 8704
#define BOFF   (2 * A128)              // 20480
#define STAGEB (2 * A128 + 2 * BMAT)   // 37888
#define SMEM_GEMM (3 * STAGEB)         // 113664

template<int EPI>
__global__ __launch_bounds__(256, 2) void mma_gemm(
    const __nv_bfloat16* __restrict__ Ah, const __nv_bfloat16* __restrict__ Al,
    const __nv_bfloat16* __restrict__ Bh, const __nv_bfloat16* __restrict__ Bl,
    const float* __restrict__ bias, const float* __restrict__ R, float* __restrict__ C,
    int ld, int ldb, int kIters, int ldc,
    __nv_bfloat16* __restrict__ Ch, __nv_bfloat16* __restrict__ Cl)
{
    extern __shared__ char smem[];
    uint32_t sm0;
    asm("{ .reg .u64 t; cvta.to.shared.u64 t, %1; cvt.u32.u64 %0, t; }" : "=r"(sm0) : "l"(smem));
    int tid = threadIdx.x, wid = tid >> 5, lane = tid & 31;
    int bn = blockIdx.x, bm = blockIdx.y;

    const __nv_bfloat16* srcs[8];
    uint32_t dsts[8];
#pragma unroll
    for (int j = 0; j < 8; j++) {
        int slot = tid + j * 256;
        if (j < 4) {
            int mat = slot >> 9;
            int r   = (slot >> 2) & 127;
            int sg  = slot & 3;
            const __nv_bfloat16* base = mat ? Al : Ah;
            srcs[j] = base + (size_t)(bm * 128 + r) * ld + sg * 8;
            dsts[j] = sm0 + mat * A128 + r * PADA + sg * 16;
        } else {
            int s2  = slot - 1024;
            int mat = s2 >> 9;
            int r   = (s2 >> 4) & 31;
            int sg  = s2 & 15;
            const __nv_bfloat16* base = mat ? Bl : Bh;
            srcs[j] = base + (size_t)r * ldb + bn * 128 + sg * 8;
            dsts[j] = sm0 + BOFF + mat * BMAT + r * PADB2 + sg * 16;
        }
    }

#define LOAD_STAGE(stg)                                                            \
    {                                                                              \
        _Pragma("unroll")                                                          \
        for (int j = 0; j < 8; j++) {                                              \
            asm volatile("cp.async.cg.shared.global [%0], [%1], 16;"               \
                         :: "r"(dsts[j] + (stg) * STAGEB), "l"(srcs[j]) : "memory"); \
            srcs[j] += (j < 4) ? 32 : (size_t)32 * ldb;                            \
        }                                                                          \
        asm volatile("cp.async.commit_group;" ::: "memory");                       \
    }

    int warp_m = wid >> 2, warp_n = wid & 3;
    int g = lane >> 2, tg = lane & 3;
    int t8 = lane >> 3, tl = lane & 7;
    uint32_t aBase = (uint32_t)((warp_m * 64 + (t8 & 1) * 8 + tl) * PADA + (t8 >> 1) * 16);
    uint32_t bBase = (uint32_t)(((t8 & 1) * 8 + tl) * PADB2 + (warp_n * 32 + (t8 >> 1) * 8) * 2);

    float acc[4][4][4];
#pragma unroll
    for (int mt = 0; mt < 4; mt++)
#pragma unroll
        for (int nt = 0; nt < 4; nt++)
#pragma unroll
            for (int j = 0; j < 4; j++) acc[mt][nt][j] = 0.f;

    LOAD_STAGE(0);
    LOAD_STAGE(1);

    for (int it = 0; it < kIters; it++) {
        asm volatile("cp.async.wait_group 1;" ::: "memory");
        __syncthreads();
        uint32_t st = sm0 + (it % 3) * STAGEB;

#pragma unroll
        for (int ks = 0; ks < 2; ks++) {
            uint32_t bh[4][2], bl[4][2];
#pragma unroll
            for (int p = 0; p < 2; p++) {
                uint32_t rb = st + BOFF + bBase + ks * (16 * PADB2) + p * 32;
                uint32_t r4[4];
                ldm4t(r4, rb);
                bh[2 * p][0] = r4[0]; bh[2 * p][1] = r4[1];
                bh[2 * p + 1][0] = r4[2]; bh[2 * p + 1][1] = r4[3];
                ldm4t(r4, rb + BMAT);
                bl[2 * p][0] = r4[0]; bl[2 * p][1] = r4[1];
                bl[2 * p + 1][0] = r4[2]; bl[2 * p + 1][1] = r4[3];
            }
#pragma unroll
            for (int mt = 0; mt < 4; mt++) {
                uint32_t ra = st + aBase + mt * (16 * PADA) + ks * 32;
                uint32_t ah[4], al[4];
                ldm4(ah, ra);
                ldm4(al, ra + A128);
#pragma unroll
                for (int nt = 0; nt < 4; nt++) {
                    mma16816(acc[mt][nt], ah, bh[nt]);
                    mma16816(acc[mt][nt], ah, bl[nt]);
                    mma16816(acc[mt][nt], al, bh[nt]);
                }
            }
        }
        if (it + 2 < kIters) {
            LOAD_STAGE((it + 2) % 3);
        } else {
            asm volatile("cp.async.commit_group;" ::: "memory");
        }
    }

#pragma unroll
    for (int mt = 0; mt < 4; mt++) {
        int row0 = bm * 128 + warp_m * 64 + mt * 16 + g;
#pragma unroll
        for (int nt = 0; nt < 4; nt++) {
            int col = bn * 128 + warp_n * 32 + nt * 8 + tg * 2;
#pragma unroll
            for (int half = 0; half < 2; half++) {
                int row = row0 + half * 8;
                float2 v = make_float2(acc[mt][nt][half * 2], acc[mt][nt][half * 2 + 1]);
                if (EPI == 1) {
                    const float2 r = *(const float2*)(R + (size_t)row * ldc + col);
                    v.x += r.x; v.y += r.y;
                }
                if (EPI == 4) {
                    const float2 b = *(const float2*)(bias + col);
                    const float2 r = *(const float2*)(R + (size_t)row * ldc + col);
                    v.x += b.x + r.x; v.y += b.y + r.y;
                }
                if (EPI == 5) {
                    const float2 b = *(const float2*)(bias + col);
                    v.x = gelu_new(v.x + b.x); v.y = gelu_new(v.y + b.y);
                    __nv_bfloat162 hh, ll;
                    split2(v.x, hh.x, ll.x);
                    split2(v.y, hh.y, ll.y);
                    *(__nv_bfloat162*)(Ch + (size_t)row * ldc + col) = hh;
                    *(__nv_bfloat162*)(Cl + (size_t)row * ldc + col) = ll;
                } else {
                    *(float2*)(C + (size_t)row * ldc + col) = v;
                }
            }
        }
    }
#undef LOAD_STAGE
}

// ================= head GEMM: 256-row tile, W read once, balanced split-K=37 =================
// bz < 14 -> 43 iters, else 42 (37*42 + 14 = 1568 total K-iters). 296 CTAs = 2/SM.
#define HPADA  80
#define HAMAT  (256 * HPADA)                   // 20480
#define HA_STAGE (2 * HAMAT)                   // 40960
#define HB_BUF   (2 * BMAT)                    // 17408
#define HB_OFF   (3 * HA_STAGE)                // 122880
#define SMEM_HEAD (HB_OFF + 2 * HB_BUF)        // 157696

__global__ __launch_bounds__(256, 1) void head_gemm(
    const __nv_bfloat16* __restrict__ Ah, const __nv_bfloat16* __restrict__ Al,
    const float* __restrict__ W, float* __restrict__ Cpart)
{
    extern __shared__ char smem[];
    uint32_t sm0;
    asm("{ .reg .u64 t; cvta.to.shared.u64 t, %1; cvt.u32.u64 %0, t; }" : "=r"(sm0) : "l"(smem));
    int tid = threadIdx.x, wid = tid >> 5, lane = tid & 31;
    int bn = blockIdx.x, bz = blockIdx.z;
    int iters = 42 + (bz < 14 ? 1 : 0);
    size_t kStart = ((size_t)bz * 42 + (bz < 14 ? bz : 14)) * 32;

    const __nv_bfloat16* asrc[8];
    uint32_t adst[8];
#pragma unroll
    for (int j = 0; j < 8; j++) {
        int slot = tid + j * 256;
        int mat = slot >> 10;
        int r   = (slot >> 2) & 255;
        int sg  = slot & 3;
        const __nv_bfloat16* base = mat ? Al : Ah;
        asrc[j] = base + (size_t)r * KHEAD + kStart + sg * 8;
        adst[j] = sm0 + mat * HAMAT + r * HPADA + sg * 16;
    }
#define LOADA(stg)                                                                \
    {                                                                             \
        _Pragma("unroll")                                                         \
        for (int j = 0; j < 8; j++) {                                             \
            asm volatile("cp.async.cg.shared.global [%0], [%1], 16;"              \
                         :: "r"(adst[j] + (stg) * HA_STAGE), "l"(asrc[j]) : "memory"); \
            asrc[j] += 32;                                                        \
        }                                                                         \
        asm volatile("cp.async.commit_group;" ::: "memory");                      \
    }

    int brow = tid >> 3, bseg = tid & 7;
    const float* bsrc = W + (kStart + brow) * 1024 + bn * 128 + bseg * 16;
    uint32_t bsm = sm0 + HB_OFF + brow * PADB2 + bseg * 32;

    int warp_m = wid >> 1, warp_n = wid & 1;
    int g = lane >> 2, tg = lane & 3;
    int t8 = lane >> 3, tl = lane & 7;
    uint32_t aBase = (uint32_t)((warp_m * 64 + (t8 & 1) * 8 + tl) * HPADA + (t8 >> 1) * 16);
    uint32_t bBase = (uint32_t)(((t8 & 1) * 8 + tl) * PADB2 + (warp_n * 64 + (t8 >> 1) * 8) * 2);

    float acc[4][8][4];
#pragma unroll
    for (int mt = 0; mt < 4; mt++)
#pragma unroll
        for (int nt = 0; nt < 8; nt++)
#pragma unroll
            for (int j = 0; j < 4; j++) acc[mt][nt][j] = 0.f;

    LOADA(0);
    LOADA(1);
    float4 br[4];
#pragma unroll
    for (int i = 0; i < 4; i++) br[i] = *(const float4*)(bsrc + i * 4);

    for (int it = 0; it < iters; it++) {
        uint32_t bd = bsm + (it & 1) * HB_BUF;
#pragma unroll
        for (int i = 0; i < 4; i++) {
            __nv_bfloat162 h0, h1, l0, l1;
            split2(br[i].x, h0.x, l0.x); split2(br[i].y, h0.y, l0.y);
            split2(br[i].z, h1.x, l1.x); split2(br[i].w, h1.y, l1.y);
            uint32_t hvx = *(uint32_t*)&h0, hvy = *(uint32_t*)&h1;
            uint32_t lvx = *(uint32_t*)&l0, lvy = *(uint32_t*)&l1;
            asm volatile("st.shared.v2.u32 [%0], {%1, %2};" :: "r"(bd + i * 8), "r"(hvx), "r"(hvy) : "memory");
            asm volatile("st.shared.v2.u32 [%0], {%1, %2};" :: "r"(bd + BMAT + i * 8), "r"(lvx), "r"(lvy) : "memory");
        }
        if (it + 1 < iters) {
            const float* nb = bsrc + (size_t)(it + 1) * 32 * 1024;
#pragma unroll
            for (int i = 0; i < 4; i++) br[i] = *(const float4*)(nb + i * 4);
        }
        asm volatile("cp.async.wait_group 1;" ::: "memory");
        __syncthreads();

        uint32_t st = sm0 + (it % 3) * HA_STAGE;
        uint32_t bb = sm0 + HB_OFF + (it & 1) * HB_BUF;
#pragma unroll
        for (int ks = 0; ks < 2; ks++) {
            uint32_t bh[8][2], bl[8][2];
#pragma unroll
            for (int p = 0; p < 4; p++) {
                uint32_t rb = bb + bBase + ks * (16 * PADB2) + p * 32;
                uint32_t r4[4];
                ldm4t(r4, rb);
                bh[2 * p][0] = r4[0]; bh[2 * p][1] = r4[1];
                bh[2 * p + 1][0] = r4[2]; bh[2 * p + 1][1] = r4[3];
                ldm4t(r4, rb + BMAT);
                bl[2 * p][0] = r4[0]; bl[2 * p][1] = r4[1];
                bl[2 * p + 1][0] = r4[2]; bl[2 * p + 1][1] = r4[3];
            }
#pragma unroll
            for (int mt = 0; mt < 4; mt++) {
                uint32_t ra = st + aBase + mt * (16 * HPADA) + ks * 32;
                uint32_t ah[4], al[4];
                ldm4(ah, ra);
                ldm4(al, ra + HAMAT);
#pragma unroll
                for (int nt = 0; nt < 8; nt++) {
                    mma16816(acc[mt][nt], ah, bh[nt]);
                    mma16816(acc[mt][nt], ah, bl[nt]);
                    mma16816(acc[mt][nt], al, bh[nt]);
                }
            }
        }
        if (it + 2 < iters) {
            LOADA((it + 2) % 3);
        } else {
            asm volatile("cp.async.commit_group;" ::: "memory");
        }
    }

    float* Cp = Cpart + (size_t)bz * (B_ * OUT_);
#pragma unroll
    for (int mt = 0; mt < 4; mt++) {
        int row0 = warp_m * 64 + mt * 16 + g;
#pragma unroll
        for (int nt = 0; nt < 8; nt++) {
            int col = bn * 128 + warp_n * 64 + nt * 8 + tg * 2;
#pragma unroll
            for (int half = 0; half < 2; half++) {
                int row = row0 + half * 8;
                *(float2*)(Cp + (size_t)row * 1024 + col) =
                    make_float2(acc[mt][nt][half * 2], acc[mt][nt][half * 2 + 1]);
            }
        }
    }
#undef LOADA
}

// ---------------- merged weight conversion ----------------
__global__ void convAll(const float* __restrict__ wq, const float* __restrict__ wk,
                        const float* __restrict__ wv, const float* __restrict__ wo,
                        const float* __restrict__ w1, const float* __restrict__ w2,
                        __nv_bfloat16* __restrict__ Wh, __nv_bfloat16* __restrict__ Wl) {
    int unit = blockIdx.x >> 10;
    int blk  = blockIdx.x & 1023;
    int layer = unit / 6, widx = unit % 6;
    const float* srcs[6] = {wq, wk, wv, wo, w1, w2};
    const float* src = srcs[widx] + (size_t)layer * D_ * D_;
    size_t idx = (size_t)blk * 1024 + threadIdx.x * 4;
    int k = (int)(idx >> 10);
    int n = (int)(idx & 1023);
    int Nout  = (widx < 3) ? 3072 : 1024;
    int coloff = (widx < 3) ? widx * 1024 : 0;
    size_t dbase = (size_t)layer * 6 * D_ * D_ + ((widx < 3) ? 0 : (size_t)widx * D_ * D_);
    size_t o = dbase + (size_t)k * Nout + coloff + n;
    float4 v = *(const float4*)(src + idx);
    __nv_bfloat162 h0, h1, l0, l1;
    split2(v.x, h0.x, l0.x); split2(v.y, h0.y, l0.y);
    split2(v.z, h1.x, l1.x); split2(v.w, h1.y, l1.y);
    *(__nv_bfloat162*)(Wh + o) = h0;
    *(__nv_bfloat162*)(Wh + o + 2) = h1;
    *(__nv_bfloat162*)(Wl + o) = l0;
    *(__nv_bfloat162*)(Wl + o + 2) = l1;
}

// ---------------- head reduce (37 partials) ----------------
__global__ void head_reduce(const float* __restrict__ parts, const float* __restrict__ bias,
                            float* __restrict__ out) {
    int i = blockIdx.x * blockDim.x + threadIdx.x;
    float s = bias[i & (OUT_ - 1)];
#pragma unroll
    for (int z = 0; z < KSPLIT; z++) s += parts[(size_t)z * (B_ * OUT_) + i];
    out[i] = fmaxf(s, 0.f);
}

// ---------------- embed ----------------
__global__ void embed_kernel(const float* __restrict__ x, const float* __restrict__ pos) {
    __shared__ float tile[64][S_ + 1];
    int b = blockIdx.y;
    int d0 = blockIdx.x * 64;
    int tid = threadIdx.x;
    for (int idx = tid; idx < 64 * S_; idx += 256) {
        int dr = idx / S_, s = idx % S_;
        tile[dr][s] = x[(size_t)(b * C_ + d0 + dr) * S_ + s];
    }
    __syncthreads();
    for (int idx = tid; idx < S_ * 64; idx += 256) {
        int s = idx >> 6, dr = idx & 63;
        g_h[(size_t)(b * S_ + s) * D_ + d0 + dr] = tile[dr][s] + pos[s * D_ + d0 + dr];
    }
}

// ---------------- layernorm (vectorized) ----------------
__global__ void ln_split_kernel(const float* __restrict__ in,
                                __nv_bfloat16* __restrict__ oh, __nv_bfloat16* __restrict__ ol,
                                const float* __restrict__ sc, const float* __restrict__ bi) {
    int row = blockIdx.x;
    int tid = threadIdx.x;
    int d0 = tid * 4;
    float4 v = *(const float4*)(in + (size_t)row * D_ + d0);
    float s = v.x + v.y + v.z + v.w;
    float ss = v.x * v.x + v.y * v.y + v.z * v.z + v.w * v.w;

    __shared__ float rs[8], rss[8];
    int lane = tid & 31, w = tid >> 5;
#pragma unroll
    for (int o = 16; o; o >>= 1) {
        s  += __shfl_xor_sync(0xffffffffu, s,  o);
        ss += __shfl_xor_sync(0xffffffffu, ss, o);
    }
    if (lane == 0) { rs[w] = s; rss[w] = ss; }
    __syncthreads();
    if (tid < 32) {
        float s2  = (tid < 8) ? rs[tid]  : 0.f;
        float ss2 = (tid < 8) ? rss[tid] : 0.f;
#pragma unroll
        for (int o = 4; o; o >>= 1) {
            s2  += __shfl_xor_sync(0xffffffffu, s2,  o);
            ss2 += __shfl_xor_sync(0xffffffffu, ss2, o);
        }
        if (tid == 0) { rs[0] = s2; rss[0] = ss2; }
    }
    __syncthreads();
    float mean = rs[0] * (1.f / 1024.f);
    float var  = rss[0] * (1.f / 1024.f) - mean * mean;
    float inv  = rsqrtf(var + 1e-5f);

    float4 scv = *(const float4*)(sc + d0);
    float4 biv = *(const float4*)(bi + d0);
    float r0 = (v.x - mean) * inv * scv.x + biv.x;
    float r1 = (v.y - mean) * inv * scv.y + biv.y;
    float r2 = (v.z - mean) * inv * scv.z + biv.z;
    float r3 = (v.w - mean) * inv * scv.w + biv.w;
    __nv_bfloat162 h0, h1, l0, l1;
    split2(r0, h0.x, l0.x); split2(r1, h0.y, l0.y);
    split2(r2, h1.x, l1.x); split2(r3, h1.y, l1.y);
    uint2 hv, lv;
    hv.x = *(uint32_t*)&h0; hv.y = *(uint32_t*)&h1;
    lv.x = *(uint32_t*)&l0; lv.y = *(uint32_t*)&l1;
    *(uint2*)(oh + (size_t)row * D_ + d0) = hv;
    *(uint2*)(ol + (size_t)row * D_ + d0) = lv;
}

// ---------------- fused attention: 4x4 register blocking ----------------
__global__ void attn_kernel() {
    int bh = blockIdx.x;
    int b  = bh >> 1;
    int hh = bh & 1;
    __shared__ float qs[52 * 65];
    __shared__ float ks[52 * 65];
    __shared__ float sc[52 * 50];
    int tid = threadIdx.x;
    const size_t baseQ = (size_t)b * S_ * 3072 + hh * HD_;

    for (int idx = tid; idx < 3 * 65; idx += 256) {
        qs[49 * 65 + idx] = 0.f;
        ks[49 * 65 + idx] = 0.f;
    }
    for (int idx = tid; idx < 3 * 50; idx += 256) sc[49 * 50 + idx] = 0.f;

    int tq = tid / 13, tk = tid - tq * 13;
    bool p1 = (tid < 169);
    int q0 = tq * 4, k0 = tk * 4;
    float acc[4][4];
#pragma unroll
    for (int i = 0; i < 4; i++)
#pragma unroll
        for (int j = 0; j < 4; j++) acc[i][j] = 0.f;

    for (int c = 0; c < 8; c++) {
        __syncthreads();
        for (int idx = tid; idx < S_ * 16; idx += 256) {
            int r = idx >> 4, f = idx & 15;
            const float* gp = g_qkv + baseQ + (size_t)r * 3072 + c * 64 + f * 4;
            float4 qv = *(const float4*)gp;
            float4 kv = *(const float4*)(gp + 1024);
            float* qd = &qs[r * 65 + f * 4];
            float* kd = &ks[r * 65 + f * 4];
            qd[0] = qv.x; qd[1] = qv.y; qd[2] = qv.z; qd[3] = qv.w;
            kd[0] = kv.x; kd[1] = kv.y; kd[2] = kv.z; kd[3] = kv.w;
        }
        __syncthreads();
        if (p1) {
#pragma unroll 4
            for (int d = 0; d < 64; d++) {
                float ra[4], rb[4];
#pragma unroll
                for (int i = 0; i < 4; i++) {
                    ra[i] = qs[(q0 + i) * 65 + d];
                    rb[i] = ks[(k0 + i) * 65 + d];
                }
#pragma unroll
                for (int i = 0; i < 4; i++)
#pragma unroll
                    for (int j = 0; j < 4; j++) acc[i][j] += ra[i] * rb[j];
            }
        }
    }
    __syncthreads();
    const float scale = 0.044194173824159216f;
    if (p1) {
#pragma unroll
        for (int i = 0; i < 4; i++)
#pragma unroll
            for (int j = 0; j < 4; j++) {
                int q = q0 + i, k = k0 + j;
                if (q < S_ && k < S_) sc[q * 50 + k] = acc[i][j] * scale;
            }
    }
    __syncthreads();

    if (tid < S_) {
        float mx = -1e30f;
        for (int k = 0; k < S_; k++) mx = fmaxf(mx, sc[tid * 50 + k]);
        float sum = 0.f;
        for (int k = 0; k < S_; k++) {
            float e = __expf(sc[tid * 50 + k] - mx);
            sc[tid * 50 + k] = e; sum += e;
        }
        float inv = 1.f / sum;
        for (int k = 0; k < S_; k++) sc[tid * 50 + k] *= inv;
    }

    int tq2 = tid >> 4, td = tid & 15;
    bool p2 = (tq2 < 13);
    int q2 = tq2 * 4, d0 = td * 4;
    const size_t baseO = (size_t)b * S_ * D_ + hh * HD_;

    for (int c = 0; c < 8; c++) {
        __syncthreads();
        for (int idx = tid; idx < S_ * 16; idx += 256) {
            int r = idx >> 4, f = idx & 15;
            float4 vv = *(const float4*)(g_qkv + baseQ + 2048 + (size_t)r * 3072 + c * 64 + f * 4);
            float* vd = &ks[r * 65 + f * 4];
            vd[0] = vv.x; vd[1] = vv.y; vd[2] = vv.z; vd[3] = vv.w;
        }
        __syncthreads();
        if (p2) {
            float a2[4][4];
#pragma unroll
            for (int i = 0; i < 4; i++)
#pragma unroll
                for (int j = 0; j < 4; j++) a2[i][j] = 0.f;
            for (int k = 0; k < S_; k++) {
                float ra[4], rb[4];
#pragma unroll
                for (int i = 0; i < 4; i++) ra[i] = sc[(q2 + i) * 50 + k];
#pragma unroll
                for (int j = 0; j < 4; j++) rb[j] = ks[k * 65 + d0 + j];
#pragma unroll
                for (int i = 0; i < 4; i++)
#pragma unroll
                    for (int j = 0; j < 4; j++) a2[i][j] += ra[i] * rb[j];
            }
#pragma unroll
            for (int i = 0; i < 4; i++) {
                int q = q2 + i;
                if (q < S_) {
                    size_t o = baseO + (size_t)q * D_ + c * 64 + d0;
                    __nv_bfloat162 h0, h1, l0, l1;
                    split2(a2[i][0], h0.x, l0.x);
                    split2(a2[i][1], h0.y, l0.y);
                    split2(a2[i][2], h1.x, l1.x);
                    split2(a2[i][3], h1.y, l1.y);
                    uint2 hv, lv;
                    hv.x = *(uint32_t*)&h0; hv.y = *(uint32_t*)&h1;
                    lv.x = *(uint32_t*)&l0; lv.y = *(uint32_t*)&l1;
                    *(uint2*)(g_ah + o) = hv;
                    *(uint2*)(g_al + o) = lv;
                }
            }
        }
    }
}

// ---------------- host orchestration ----------------
extern "C" void kernel_launch(void* const* d_in, const int* in_sizes, int n_in,
                              void* d_out, int out_size) {
    (void)in_sizes; (void)n_in; (void)out_size;
    const float* x      = (const float*)d_in[0];
    const float* pos    = (const float*)d_in[1];
    const float* ln1_s  = (const float*)d_in[2];
    const float* ln1_b  = (const float*)d_in[3];
    const float* wq     = (const float*)d_in[4];
    const float* wk     = (const float*)d_in[5];
    const float* wv     = (const float*)d_in[6];
    const float* wo     = (const float*)d_in[7];
    const float* ln2_s  = (const float*)d_in[8];
    const float* ln2_b  = (const float*)d_in[9];
    const float* w1     = (const float*)d_in[10];
    const float* b1     = (const float*)d_in[11];
    const float* w2     = (const float*)d_in[12];
    const float* b2     = (const float*)d_in[13];
    const float* lnf_s  = (const float*)d_in[14];
    const float* lnf_b  = (const float*)d_in[15];
    const float* head_w = (const float*)d_in[16];
    const float* head_b = (const float*)d_in[17];
    float* out = (float*)d_out;

    float *pH, *pQKV, *pPart;
    __nv_bfloat16 *pAh, *pAl, *pBh, *pBl, *pWh, *pWl;
    cudaGetSymbolAddress((void**)&pH,   g_h);
    cudaGetSymbolAddress((void**)&pQKV, g_qkv);
    cudaGetSymbolAddress((void**)&pAh,  g_ah);
    cudaGetSymbolAddress((void**)&pAl,  g_al);
    cudaGetSymbolAddress((void**)&pBh,  g_bh);
    cudaGetSymbolAddress((void**)&pBl,  g_bl);
    cudaGetSymbolAddress((void**)&pWh,  g_wh);
    cudaGetSymbolAddress((void**)&pWl,  g_wl);
    cudaGetSymbolAddress((void**)&pPart, g_part);

    cudaFuncSetAttribute(mma_gemm<0>, cudaFuncAttributeMaxDynamicSharedMemorySize, SMEM_GEMM);
    cudaFuncSetAttribute(mma_gemm<1>, cudaFuncAttributeMaxDynamicSharedMemorySize, SMEM_GEMM);
    cudaFuncSetAttribute(mma_gemm<4>, cudaFuncAttributeMaxDynamicSharedMemorySize, SMEM_GEMM);
    cudaFuncSetAttribute(mma_gemm<5>, cudaFuncAttributeMaxDynamicSharedMemorySize, SMEM_GEMM);
    cudaFuncSetAttribute(head_gemm, cudaFuncAttributeMaxDynamicSharedMemorySize, SMEM_HEAD);

    const size_t LWB = (size_t)6 * D_ * D_;
    const dim3 gQKV(24, 98);
    const dim3 gStd(8, 98);

    convAll<<<12 * 1024, 256>>>(wq, wk, wv, wo, w1, w2, pWh, pWl);
    embed_kernel<<<dim3(D_ / 64, B_), 256>>>(x, pos);

    for (int i = 0; i < L_; i++) {
        const __nv_bfloat16* Wh = pWh + i * LWB;
        const __nv_bfloat16* Wl = pWl + i * LWB;
        ln_split_kernel<<<M_, 256>>>(pH, pAh, pAl, ln1_s + i * D_, ln1_b + i * D_);
        mma_gemm<0><<<gQKV, 256, SMEM_GEMM>>>(pAh, pAl, Wh, Wl, nullptr, nullptr, pQKV,
                                              D_, 3072, 32, 3072, nullptr, nullptr);
        attn_kernel<<<B_ * H_, 256>>>();
        mma_gemm<1><<<gStd, 256, SMEM_GEMM>>>(pAh, pAl, Wh + 3 * (size_t)D_ * D_, Wl + 3 * (size_t)D_ * D_,
                                              nullptr, pH, pH, D_, 1024, 32, 1024, nullptr, nullptr);
        ln_split_kernel<<<M_, 256>>>(pH, pAh, pAl, ln2_s + i * D_, ln2_b + i * D_);
        mma_gemm<5><<<gStd, 256, SMEM_GEMM>>>(pAh, pAl, Wh + 4 * (size_t)D_ * D_, Wl + 4 * (size_t)D_ * D_,
                                              b1 + i * FF_, nullptr, nullptr, D_, 1024, 32, 1024, pBh, pBl);
        mma_gemm<4><<<gStd, 256, SMEM_GEMM>>>(pBh, pBl, Wh + 5 * (size_t)D_ * D_, Wl + 5 * (size_t)D_ * D_,
                                              b2 + i * D_, pH, pH, FF_, 1024, 32, 1024, nullptr, nullptr);
    }

    ln_split_kernel<<<M_, 256>>>(pH, pAh, pAl, lnf_s, lnf_b);

    // head: 256-row tile, W read once, balanced split-K = 37 (296 CTAs = 2/SM)
    head_gemm<<<dim3(8, 1, KSPLIT), 256, SMEM_HEAD>>>(pAh, pAl, head_w, pPart);
    head_reduce<<<B_ * OUT_ / 256, 256>>>(pPart, head_b, out);
}